// round 14
// baseline (speedup 1.0000x reference)
#include <cuda_runtime.h>
#include <math.h>

#define N_IMG   512
#define N_ANG   25
#define N_DET   512
#define N_SAMP  1024
#define N_RAYS  (N_ANG * N_DET)
#define TB      514              // bordered coords: gq = g0+1, fq = f0+1, in [0, 513]
#define TBH     257              // g pair-row count

#define SRC_DIST 512.0f
#define DET_DIST 512.0f
#define DET_SPACING 3.0f

// Row-pair interleaved differential quad tables:
// slot(gq,fq) = ((gq>>1)*TB + fq)*2 + (gq&1)  -> 128B line = 4(f) x 2(g) footprint.
// Payload: .x=v00 .y=v01-v00 .z=v10-v00 .w=v11-v10-v01+v00 ; bilinear = .x+wf*.y+wg*(.z+wf*.w)
//  g_quadB : g = image row, f = image col ; g_quadBT: g = col, f = row (v(g,f)=img[f][g])
__device__ float4 g_quadB [TBH * TB * 2];
__device__ float4 g_quadBT[TBH * TB * 2];

__device__ __forceinline__ float4 diffquad(float a, float b, float c, float d) {
    return make_float4(a, b - a, c - a, (d - c) - (b - a));
}

// Tile: 32 g x 32 f quad entries per block; smem = 33x33 source patch.
// Lane->slot mapping is identity-contiguous: each STG.128 writes 32
// consecutive slots = 512B fully coalesced.
__global__ __launch_bounds__(256)
void prep_kernel(const float* __restrict__ img) {
    __shared__ float sm[33][33];
    int tx = threadIdx.x;              // 0..31
    int ty = threadIdx.y;              // 0..7
    int fbase = blockIdx.x * 32;       // fq tile base
    int gbase = blockIdx.y * 32;       // gq tile base (16 pair-rows)
    int z = blockIdx.z;

    int gs = gbase - 1, fs = fbase - 1;
    bool interior = (gs >= 0) & (fs >= 0) & (gs + 32 < N_IMG) & (fs + 32 < N_IMG);

    if (interior) {
        if (z == 0) {
            #pragma unroll
            for (int a = ty; a < 33; a += 8) {
                const float* rp = img + (gs + a) * N_IMG + fs;
                sm[a][tx] = rp[tx];
                if (tx == 0) sm[a][32] = rp[32];
            }
        } else {
            #pragma unroll
            for (int b = ty; b < 33; b += 8) {
                const float* rp = img + (fs + b) * N_IMG + gs;
                sm[tx][b] = rp[tx];
                if (tx == 0) sm[32][b] = rp[32];
            }
        }
    } else {
        if (z == 0) {
            for (int a = ty; a < 33; a += 8) {
                int r = gs + a;
                bool rok = (r >= 0) & (r < N_IMG);
                for (int b = tx; b < 33; b += 32) {
                    int c = fs + b;
                    sm[a][b] = (rok && c >= 0 && c < N_IMG) ? img[r * N_IMG + c] : 0.0f;
                }
            }
        } else {
            for (int b = ty; b < 33; b += 8) {
                int r = fs + b;
                bool rok = (r >= 0) & (r < N_IMG);
                for (int a = tx; a < 33; a += 32) {
                    int c = gs + a;
                    sm[a][b] = (rok && c >= 0 && c < N_IMG) ? img[r * N_IMG + c] : 0.0f;
                }
            }
        }
    }
    __syncthreads();

    float4* __restrict__ dst = z ? g_quadBT : g_quadB;

    int p  = tx & 1;                 // g parity handled by this lane
    int fl = tx >> 1;                // f sub-index (0..15)
    int gpair_base = blockIdx.y * 16;

    #pragma unroll
    for (int it = ty; it < 32; it += 8) {
        int pl = it >> 1;            // pair-row 0..15
        int h  = it & 1;             // f half 0..1
        int ff = h * 16 + fl;        // local f 0..31
        int gg = 2 * pl + p;         // local g 0..31
        int fq = fbase + ff;
        int gq = gbase + gg;
        if (fq < TB && gq < TB) {
            float4 q = diffquad(sm[gg][ff], sm[gg][ff + 1],
                                sm[gg + 1][ff], sm[gg + 1][ff + 1]);
            dst[(((gpair_base + pl) * TB) + fq) * 2 + p] = q;
        }
    }
}

// shrink [u0,u1] so that p + u*v stays within [lo, hi]
__device__ __forceinline__ void clip_axis(float p, float v, float lo, float hi,
                                          float& u0, float& u1) {
    if (fabsf(v) < 1e-12f) {
        if (p < lo || p > hi) { u0 = 1e30f; u1 = -1e30f; }
    } else {
        float inv = __fdividef(1.0f, v);
        float a = (lo - p) * inv;
        float b = (hi - p) * inv;
        float mn = fminf(a, b), mx = fmaxf(a, b);
        u0 = fmaxf(u0, mn);
        u1 = fminf(u1, mx);
    }
}

// One ray per warp; detector STRIDED across warps of a block so each block's
// 8 rays sample the full detector range (uniform block durations, no ragged
// wave-2 tail). Per angle: 64 blocks; block q holds detectors q + 64*w.
__global__ __launch_bounds__(256)
void fanbeam_kernel(float* __restrict__ out) {
    int w    = threadIdx.x >> 5;
    int lane = threadIdx.x & 31;

    int a = blockIdx.x >> 6;            // angle (25)
    int q = blockIdx.x & 63;            // block-within-angle
    int d = q + (w << 6);               // strided detector

    float beta = (float)a * (2.0f * 3.14159265358979323846f / (float)N_ANG);
    float s, c;
    sincosf(beta, &s, &c);

    float t  = ((float)d - (float)(N_DET - 1) * 0.5f) * DET_SPACING;
    float sx = -SRC_DIST * s;
    float sy =  SRC_DIST * c;
    float dx = t * c + DET_DIST * s - sx;
    float dy = t * s - DET_DIST * c - sy;
    float seg = sqrtf(dx * dx + dy * dy);

    const float half  = (float)(N_IMG - 1) * 0.5f;   // 255.5
    const float inv_s = 1.0f / (float)N_SAMP;
    float cA = sx + half;          // col(u) = cA + u*dx
    float rA = half - sy;          // row(u) = rA - u*dy

    float dxs = dx * inv_s;
    float dys = -dy * inv_s;
    float cA0 = fmaf(0.5f, dxs, cA);
    float rA0 = fmaf(0.5f, dys, rA);

    // orientation: fast axis = larger per-sample step; +1 shift to table coords
    bool swp = fabsf(dys) > fabsf(dxs);
    float fA0 = (swp ? rA0 : cA0) + 1.0f;
    float fds = swp ? dys : dxs;
    float gA0 = (swp ? cA0 : rA0) + 1.0f;
    float gds = swp ? dxs : dys;

    // single clip: coords in [-0.998, 512] -> floor in [-1, 512]
    float u0 = 0.0f, u1 = 1.0f;
    clip_axis(cA,  dx, -0.998f, 512.0f, u0, u1);
    clip_axis(rA, -dy, -0.998f, 512.0f, u0, u1);

    int s0 = max(0,          (int)ceilf (u0 * (float)N_SAMP - 0.5f));
    int s1 = min(N_SAMP - 1, (int)floorf(u1 * (float)N_SAMP - 0.5f));
    bool live = (u0 <= u1);

    // ---- all setup done; wait for prep_kernel's tables (PDL) ----
#if __CUDA_ARCH__ >= 900
    cudaGridDependencySynchronize();
#endif

    const float4* __restrict__ tab = swp ? g_quadBT : g_quadB;

    float acc = 0.0f;
    if (live) {
        #pragma unroll 4
        for (int i = s0 + lane; i <= s1; i += 32) {
            float fi = (float)i;
            float fp = fmaf(fi, fds, fA0);   // table coords (>= 0)
            float gp = fmaf(fi, gds, gA0);
            float fqf = floorf(fp);
            float gqf = floorf(gp);
            float wf = fp - fqf;
            float wg = gp - gqf;
            int fq = (int)fqf;
            int gq = (int)gqf;
            int slot = ((gq >> 1) * TB + fq) * 2 + (gq & 1);
            float4 qd = __ldg(tab + slot);
            float u1v = fmaf(wf, qd.y, qd.x);
            float u2v = fmaf(wf, qd.w, qd.z);
            acc      += fmaf(wg, u2v, u1v);
        }
    }

    #pragma unroll
    for (int o = 16; o > 0; o >>= 1)
        acc += __shfl_down_sync(0xffffffffu, acc, o);

    if (lane == 0)
        out[a * N_DET + d] = acc * seg * inv_s;
}

extern "C" void kernel_launch(void* const* d_in, const int* in_sizes, int n_in,
                              void* d_out, int out_size) {
    (void)in_sizes; (void)n_in; (void)out_size;
    const float* img = (const float*)d_in[0];
    float* out = (float*)d_out;

    dim3 tb(32, 8);
    dim3 tg(17, 17, 2);
    prep_kernel<<<tg, tb>>>(img);

    cudaLaunchConfig_t cfg = {};
    cfg.gridDim  = dim3(N_RAYS / 8, 1, 1);   // 1600 blocks, 1 ray per warp
    cfg.blockDim = dim3(256, 1, 1);
    cfg.dynamicSmemBytes = 0;
    cudaLaunchAttribute attr[1];
    attr[0].id = cudaLaunchAttributeProgrammaticStreamSerialization;
    attr[0].val.programmaticStreamSerializationAllowed = 1;
    cfg.attrs = attr;
    cfg.numAttrs = 1;
    cudaLaunchKernelEx(&cfg, fanbeam_kernel, out);
}

// round 15
// speedup vs baseline: 1.1366x; 1.1366x over previous
#include <cuda_runtime.h>
#include <cuda_fp16.h>
#include <math.h>

#define N_IMG   512
#define N_ANG   25
#define N_DET   512
#define N_SAMP  1024
#define N_RAYS  (N_ANG * N_DET)
#define TB      514              // bordered coords: gq = g0+1, fq = f0+1, in [0, 513]
#define TBQ     129              // ceil(TB/4) g quad-row groups

#define SRC_DIST 512.0f
#define DET_DIST 512.0f
#define DET_SPACING 3.0f

// FP16 differential quad tables, 4(f) x 4(g) line interleave.
// Entry for (gq,fq) at slot = ((gq>>2)*TB + fq)*4 + (gq&3); 8 bytes each
// (uint2 = two half2) -> one 128B cache line covers a 4x4 coord footprint.
// Payload (halves): h0=v00 h1=v01-v00 h2=v10-v00 h3=v11-v10-v01+v00,
// computed in fp32 from the zero-padded image, rounded to fp16.
// bilinear(wf,wg) = h0 + wf*h1 + wg*(h2 + wf*h3)
//  g_quadB : g = image row, f = image col ; g_quadBT: g = col, f = row (v(g,f)=img[f][g])
__device__ uint2 g_quadB [TBQ * TB * 4];
__device__ uint2 g_quadBT[TBQ * TB * 4];

__device__ __forceinline__ uint2 diffquad_h(float a, float b, float c, float d) {
    // a=v00 b=v01 c=v10 d=v11
    __half2 lo = __floats2half2_rn(a, b - a);
    __half2 hi = __floats2half2_rn(c - a, (d - c) - (b - a));
    uint2 r;
    r.x = *reinterpret_cast<unsigned int*>(&lo);
    r.y = *reinterpret_cast<unsigned int*>(&hi);
    return r;
}

// Tile: 32 g x 32 f quad entries per block; smem = 33x33 source patch.
// Lane mapping gpar=l&3, fl=l>>2 makes slot offsets IDENTITY-contiguous
// across lanes: each warp store = 32 consecutive 8B slots = 256B coalesced.
__global__ __launch_bounds__(256)
void prep_kernel(const float* __restrict__ img) {
    __shared__ float sm[33][33];
    int tx = threadIdx.x;              // 0..31
    int ty = threadIdx.y;              // 0..7
    int fbase = blockIdx.x * 32;       // fq tile base
    int gbase = blockIdx.y * 32;       // gq tile base
    int z = blockIdx.z;

    int gs = gbase - 1, fs = fbase - 1;
    bool interior = (gs >= 0) & (fs >= 0) & (gs + 32 < N_IMG) & (fs + 32 < N_IMG);

    if (interior) {
        if (z == 0) {
            #pragma unroll
            for (int a = ty; a < 33; a += 8) {
                const float* rp = img + (gs + a) * N_IMG + fs;
                sm[a][tx] = rp[tx];
                if (tx == 0) sm[a][32] = rp[32];
            }
        } else {
            #pragma unroll
            for (int b = ty; b < 33; b += 8) {
                const float* rp = img + (fs + b) * N_IMG + gs;
                sm[tx][b] = rp[tx];
                if (tx == 0) sm[32][b] = rp[32];
            }
        }
    } else {
        if (z == 0) {
            for (int a = ty; a < 33; a += 8) {
                int r = gs + a;
                bool rok = (r >= 0) & (r < N_IMG);
                for (int b = tx; b < 33; b += 32) {
                    int c = fs + b;
                    sm[a][b] = (rok && c >= 0 && c < N_IMG) ? img[r * N_IMG + c] : 0.0f;
                }
            }
        } else {
            for (int b = ty; b < 33; b += 8) {
                int r = fs + b;
                bool rok = (r >= 0) & (r < N_IMG);
                for (int a = tx; a < 33; a += 32) {
                    int c = gs + a;
                    sm[a][b] = (rok && c >= 0 && c < N_IMG) ? img[r * N_IMG + c] : 0.0f;
                }
            }
        }
    }
    __syncthreads();

    uint2* __restrict__ dst = z ? g_quadBT : g_quadB;

    int gpar = tx & 3;                 // g-within-quad handled by this lane
    int fl   = tx >> 2;                // f sub-index (0..7)
    int gquad_base = blockIdx.y * 8;   // gq>>2 base for this tile

    // 8 g-quads x 4 f-eighths = 32 (gblk, fh) combos; ty strides them
    #pragma unroll
    for (int it = ty; it < 32; it += 8) {
        int gblk = it >> 2;            // g quad-group 0..7
        int fh   = it & 3;             // f eighth 0..3
        int ff = fh * 8 + fl;          // local f 0..31
        int gg = gblk * 4 + gpar;      // local g 0..31
        int fq = fbase + ff;
        int gq = gbase + gg;
        if (fq < TB && gq < TB) {
            uint2 q = diffquad_h(sm[gg][ff], sm[gg][ff + 1],
                                 sm[gg + 1][ff], sm[gg + 1][ff + 1]);
            // slot = ((gq>>2)*TB + fq)*4 + gpar ; consecutive across lanes
            dst[(((gquad_base + gblk) * TB) + fq) * 4 + gpar] = q;
        }
    }
}

// shrink [u0,u1] so that p + u*v stays within [lo, hi]
__device__ __forceinline__ void clip_axis(float p, float v, float lo, float hi,
                                          float& u0, float& u1) {
    if (fabsf(v) < 1e-12f) {
        if (p < lo || p > hi) { u0 = 1e30f; u1 = -1e30f; }
    } else {
        float inv = __fdividef(1.0f, v);
        float a = (lo - p) * inv;
        float b = (hi - p) * inv;
        float mn = fminf(a, b), mx = fmaxf(a, b);
        u0 = fmaxf(u0, mn);
        u1 = fminf(u1, mx);
    }
}

// One ray per warp, 8 ADJACENT detectors per block (uniform intra-block
// durations — R14 showed striding kills block retirement).
__global__ __launch_bounds__(256)
void fanbeam_kernel(float* __restrict__ out) {
    int gwarp = blockIdx.x * 8 + (threadIdx.x >> 5);
    int lane  = threadIdx.x & 31;

    int a = gwarp >> 9;            // / N_DET (512)
    int d = gwarp & (N_DET - 1);

    float beta = (float)a * (2.0f * 3.14159265358979323846f / (float)N_ANG);
    float s, c;
    sincosf(beta, &s, &c);

    float t  = ((float)d - (float)(N_DET - 1) * 0.5f) * DET_SPACING;
    float sx = -SRC_DIST * s;
    float sy =  SRC_DIST * c;
    float dx = t * c + DET_DIST * s - sx;
    float dy = t * s - DET_DIST * c - sy;
    float seg = sqrtf(dx * dx + dy * dy);

    const float half  = (float)(N_IMG - 1) * 0.5f;   // 255.5
    const float inv_s = 1.0f / (float)N_SAMP;
    float cA = sx + half;          // col(u) = cA + u*dx
    float rA = half - sy;          // row(u) = rA - u*dy

    float dxs = dx * inv_s;
    float dys = -dy * inv_s;
    float cA0 = fmaf(0.5f, dxs, cA);
    float rA0 = fmaf(0.5f, dys, rA);

    // orientation: fast axis = larger per-sample step; +1 shift to table coords
    bool swp = fabsf(dys) > fabsf(dxs);
    float fA0 = (swp ? rA0 : cA0) + 1.0f;
    float fds = swp ? dys : dxs;
    float gA0 = (swp ? cA0 : rA0) + 1.0f;
    float gds = swp ? dxs : dys;

    // single clip: coords in [-0.998, 512] -> floor in [-1, 512]
    float u0 = 0.0f, u1 = 1.0f;
    clip_axis(cA,  dx, -0.998f, 512.0f, u0, u1);
    clip_axis(rA, -dy, -0.998f, 512.0f, u0, u1);

    int s0 = max(0,          (int)ceilf (u0 * (float)N_SAMP - 0.5f));
    int s1 = min(N_SAMP - 1, (int)floorf(u1 * (float)N_SAMP - 0.5f));
    bool live = (u0 <= u1);

    // ---- all setup done; wait for prep_kernel's tables (PDL) ----
#if __CUDA_ARCH__ >= 900
    cudaGridDependencySynchronize();
#endif

    const uint2* __restrict__ tab = swp ? g_quadBT : g_quadB;

    float acc = 0.0f;
    if (live) {
        #pragma unroll 4
        for (int i = s0 + lane; i <= s1; i += 32) {
            float fi = (float)i;
            float fp = fmaf(fi, fds, fA0);   // table coords (>= 0)
            float gp = fmaf(fi, gds, gA0);
            float fqf = floorf(fp);
            float gqf = floorf(gp);
            float wf = fp - fqf;
            float wg = gp - gqf;
            int fq = (int)fqf;
            int gq = (int)gqf;
            int slot = ((gq >> 2) * TB + fq) * 4 + (gq & 3);
            uint2 raw = __ldg(tab + slot);
            float2 q01 = __half22float2(*reinterpret_cast<__half2*>(&raw.x));
            float2 q23 = __half22float2(*reinterpret_cast<__half2*>(&raw.y));
            float u1v = fmaf(wf, q01.y, q01.x);
            float u2v = fmaf(wf, q23.y, q23.x);
            acc      += fmaf(wg, u2v, u1v);
        }
    }

    #pragma unroll
    for (int o = 16; o > 0; o >>= 1)
        acc += __shfl_down_sync(0xffffffffu, acc, o);

    if (lane == 0)
        out[gwarp] = acc * seg * inv_s;
}

extern "C" void kernel_launch(void* const* d_in, const int* in_sizes, int n_in,
                              void* d_out, int out_size) {
    (void)in_sizes; (void)n_in; (void)out_size;
    const float* img = (const float*)d_in[0];
    float* out = (float*)d_out;

    dim3 tb(32, 8);
    dim3 tg(17, 17, 2);
    prep_kernel<<<tg, tb>>>(img);

    cudaLaunchConfig_t cfg = {};
    cfg.gridDim  = dim3(N_RAYS / 8, 1, 1);   // 1600 blocks, 1 ray per warp
    cfg.blockDim = dim3(256, 1, 1);
    cfg.dynamicSmemBytes = 0;
    cudaLaunchAttribute attr[1];
    attr[0].id = cudaLaunchAttributeProgrammaticStreamSerialization;
    attr[0].val.programmaticStreamSerializationAllowed = 1;
    cfg.attrs = attr;
    cfg.numAttrs = 1;
    cudaLaunchKernelEx(&cfg, fanbeam_kernel, out);
}